// round 7
// baseline (speedup 1.0000x reference)
#include <cuda_runtime.h>
#include <math.h>

// Shapes
// x:  [32, 112, 112, 128] fp32  -> B=32, HW=12544, C=128
// w1: [128, 2048], b1: [2048], w2: [2048, 128], b2: [128]
#define B      32
#define HW     12544
#define C      128
#define R      2048
#define NSPLIT 98
#define NTOTAL (B * NSPLIT)                  // 3136 splits
#define F4_PER_B   (HW * C / 4)              // 401408 float4 per batch
#define F4_PER_BLK (128 * C / 4)             // 4096 float4 per split
#define GRID   148
#define TPB    512

// Scratch (device globals: allocation-free, zero-initialized once)
__device__ __align__(16) float g_partial[NTOTAL * C];   // 1.6 MB pool partials
__device__ __align__(16) float g_gate[B * C];           // final gates
__device__ unsigned g_cnt  = 0;                         // barrier arrival counter
__device__ volatile unsigned g_flag = 0;                // barrier sense flag
__device__ unsigned g_c0 = 0;                           // phase-1 work counter
__device__ unsigned g_c1 = 0;                           // phase-3 work counter

// Sense-reversing grid barrier. Exactly 2 calls per launch => g_flag returns
// to its initial value, so graph replays see consistent state. The barrier-1
// last-arriver resets both work counters (phase-1 grabs are complete by then;
// phase-3 counter is stale from the previous replay and unused until after).
__device__ __forceinline__ void grid_barrier(unsigned sense, bool reset_work) {
    __threadfence();          // publish this thread's phase writes
    __syncthreads();
    if (threadIdx.x == 0) {
        unsigned old = atomicAdd(&g_cnt, 1);
        if (old == GRID - 1) {
            g_cnt = 0;
            if (reset_work) { g_c0 = 0; g_c1 = 0; }
            __threadfence();
            g_flag = sense ^ 1;
        } else {
            while (g_flag == sense) { __nanosleep(64); }
        }
        __threadfence();      // acquire
    }
    __syncthreads();
}

__global__ __launch_bounds__(TPB, 1)
void se_persistent_kernel(const float* __restrict__ x,
                          const float* __restrict__ w1, const float* __restrict__ b1,
                          const float* __restrict__ w2, const float* __restrict__ b2,
                          float* __restrict__ out) {
    const int t = threadIdx.x;
    const int bid = blockIdx.x;
    unsigned sense = 0;

    __shared__ unsigned sh_idx;
    __shared__ float4 shp[TPB];          // pool reduction (8 KB)
    __shared__ float s_mean[C];
    __shared__ float h[R];               // GELU activations (8 KB)
    __shared__ float red[TPB];           // gemm2 split-K reduce

    // ---------------- Phase 1: pooling partial sums (work-stolen) ----------
    for (;;) {
        if (t == 0) sh_idx = atomicAdd(&g_c0, 1);
        __syncthreads();
        const unsigned sidx = sh_idx;
        if (sidx >= NTOTAL) break;
        const int b = sidx / NSPLIT;
        const int split = sidx % NSPLIT;
        const float4* __restrict__ xb =
            reinterpret_cast<const float4*>(x) + (size_t)b * F4_PER_B + (size_t)split * F4_PER_BLK;

        // 4096 float4 / 512 threads = 8 each; channel group fixed (512%32==0)
        float4 acc = make_float4(0.f, 0.f, 0.f, 0.f);
#pragma unroll
        for (int i = 0; i < 8; i++) {
            float4 v = xb[t + i * TPB];
            acc.x += v.x; acc.y += v.y; acc.z += v.z; acc.w += v.w;
        }
        shp[t] = acc;
        __syncthreads();
        if (t < 32) {
            float4 ssum = shp[t];
#pragma unroll
            for (int j = 1; j < 16; j++) {
                float4 v = shp[t + j * 32];
                ssum.x += v.x; ssum.y += v.y; ssum.z += v.z; ssum.w += v.w;
            }
            reinterpret_cast<float4*>(g_partial)[(size_t)sidx * 32 + t] = ssum;
        }
        __syncthreads();   // protect shp/sh_idx before next grab
    }

    grid_barrier(sense, /*reset_work=*/true);
    sense ^= 1;

    // ---------------- Phase 2: excite, one block per batch ------------------
    if (bid < B) {
        const int b = bid;

        // a) reduce pool partials -> mean s[128]
        if (t < C) {
            const float* p = g_partial + (size_t)b * NSPLIT * C + t;
            float acc = 0.f;
#pragma unroll 14
            for (int k = 0; k < NSPLIT; k++) acc += p[(size_t)k * C];
            s_mean[t] = acc * (1.0f / (float)HW);
        }
        __syncthreads();

        // b) GEMM1 + tanh-approx GELU: 4 r's per thread (r = t + k*512, coalesced)
#pragma unroll
        for (int k = 0; k < 4; k++) {
            const int r = t + k * TPB;
            float acc = b1[r];
#pragma unroll 16
            for (int c = 0; c < C; c++) acc += s_mean[c] * w1[(size_t)c * R + r];
            float u = acc;
            float inner = 0.7978845608028654f * (u + 0.044715f * u * u * u);
            h[r] = 0.5f * u * (1.0f + tanhf(inner));
        }
        __syncthreads();

        // c) GEMM2 split-K in-block: slice = t/128 (512 r's each), c = t%128
        {
            const int c = t & (C - 1);
            const int slice = t >> 7;
            const int r0 = slice * (R / 4);
            const float* w2s = w2 + (size_t)r0 * C + c;
            float acc = 0.f;
#pragma unroll 16
            for (int r = 0; r < R / 4; r++) acc += h[r0 + r] * w2s[(size_t)r * C];
            red[t] = acc;
        }
        __syncthreads();
        if (t < C) {
            float a = red[t] + red[t + 128] + red[t + 256] + red[t + 384] + b2[t];
            g_gate[b * C + t] = 1.0f / (1.0f + __expf(-a));
        }
    }

    grid_barrier(sense, /*reset_work=*/false);
    sense ^= 1;

    // ---------------- Phase 3: scale, globally reversed order ---------------
    const int c4 = (t * 4) & (C - 1);    // fixed channel group per thread
    for (;;) {
        if (t == 0) sh_idx = atomicAdd(&g_c1, 1);
        __syncthreads();
        const unsigned i = sh_idx;
        if (i >= NTOTAL) break;
        const unsigned sidx = (NTOTAL - 1) - i;        // reverse of pool order
        const int b = sidx / NSPLIT;
        const int split = sidx % NSPLIT;

        const float4 g4 = *reinterpret_cast<const float4*>(g_gate + b * C + c4);

        const size_t base = (size_t)b * F4_PER_B + (size_t)split * F4_PER_BLK;
        const float4* __restrict__ xi = reinterpret_cast<const float4*>(x) + base;
        float4* __restrict__ xo = reinterpret_cast<float4*>(out) + base;
#pragma unroll
        for (int k = 0; k < 8; k++) {
            float4 v = __ldcs(&xi[t + k * TPB]);       // dead after use: evict-first
            v.x *= g4.x; v.y *= g4.y; v.z *= g4.z; v.w *= g4.w;
            __stcs(&xo[t + k * TPB], v);               // streaming store
        }
        __syncthreads();   // protect sh_idx before next grab
    }
}

extern "C" void kernel_launch(void* const* d_in, const int* in_sizes, int n_in,
                              void* d_out, int out_size) {
    const float* x  = (const float*)d_in[0];
    const float* w1 = (const float*)d_in[1];
    const float* b1 = (const float*)d_in[2];
    const float* w2 = (const float*)d_in[3];
    const float* b2 = (const float*)d_in[4];
    float* out = (float*)d_out;

    se_persistent_kernel<<<GRID, TPB>>>(x, w1, b1, w2, b2, out);
}

// round 8
// speedup vs baseline: 1.5215x; 1.5215x over previous
#include <cuda_runtime.h>
#include <math.h>

// Shapes
// x:  [32, 112, 112, 128] fp32  -> B=32, HW=12544, C=128
// w1: [128, 2048], b1: [2048], w2: [2048, 128], b2: [128]
#define B      32
#define HW     12544
#define C      128
#define R      2048
#define NSPLIT 98
#define NTOTAL (B * NSPLIT)                  // 3136 splits of 128 rows
#define F4_PER_B   (HW * C / 4)              // 401408 float4 per batch
#define F4_PER_BLK (128 * C / 4)             // 4096 float4 per split
#define GRID   592                           // 4 blocks/SM * 148 SMs (all resident)
#define TPB    256
#define NEXCITE 256                          // excite blocks: 32 b * 8 r-chunks
#define CACHE_CUT (NTOTAL - 1800)            // last 1800 splits (~115MB) kept in L2

// Scratch (device globals: allocation-free)
__device__ __align__(16) float g_partial[NTOTAL * C];   // 1.6 MB pool partials
__device__ __align__(16) float g_gp[B * 8 * C];         // gate partials (128 KB)
__device__ unsigned g_cnt = 0;                          // barrier arrival counter
__device__ volatile unsigned g_flag = 0;                // barrier sense flag

// Sense-reversing grid barrier: exactly 2 calls per launch, so g_flag returns
// to 0 after every launch -> graph-replay safe. No work counters (static
// assignment), so nothing else to reset.
__device__ __forceinline__ void grid_barrier(unsigned sense) {
    __threadfence();
    __syncthreads();
    if (threadIdx.x == 0) {
        unsigned old = atomicAdd(&g_cnt, 1);
        if (old == GRID - 1) {
            g_cnt = 0;
            __threadfence();
            g_flag = sense ^ 1;
        } else {
            while (g_flag == sense) { __nanosleep(64); }
        }
        __threadfence();
    }
    __syncthreads();
}

__global__ __launch_bounds__(TPB, 4)
void se_persistent_kernel(const float* __restrict__ x,
                          const float* __restrict__ w1, const float* __restrict__ b1,
                          const float* __restrict__ w2, const float* __restrict__ b2,
                          float* __restrict__ out) {
    const int t = threadIdx.x;
    const int bid = blockIdx.x;

    __shared__ float4 shp[TPB];      // 4 KB pool reduction
    __shared__ float s_mean[C];
    __shared__ float h_sh[TPB];      // GELU chunk
    __shared__ float red[TPB];

    // ---------------- Phase 1: pooling partial sums (static stride) ---------
    // Channel group per thread is fixed (t + i*256, 256 % 32 == 0).
    for (unsigned sidx = bid; sidx < NTOTAL; sidx += GRID) {
        const int b = sidx / NSPLIT;
        const int split = sidx % NSPLIT;
        const float4* __restrict__ xb =
            reinterpret_cast<const float4*>(x) + (size_t)b * F4_PER_B + (size_t)split * F4_PER_BLK;

        float4 acc = make_float4(0.f, 0.f, 0.f, 0.f);
        if (sidx < CACHE_CUT) {
            // phase 3 reads this split last -> don't pollute L2
#pragma unroll
            for (int i = 0; i < 16; i++) {
                float4 v = __ldcs(&xb[t + i * TPB]);
                acc.x += v.x; acc.y += v.y; acc.z += v.z; acc.w += v.w;
            }
        } else {
            // phase 3 reads this split first (reversed order) -> keep in L2
#pragma unroll
            for (int i = 0; i < 16; i++) {
                float4 v = xb[t + i * TPB];
                acc.x += v.x; acc.y += v.y; acc.z += v.z; acc.w += v.w;
            }
        }
        shp[t] = acc;
        __syncthreads();
        if (t < 32) {
            float4 s = shp[t];
#pragma unroll
            for (int j = 1; j < 8; j++) {
                float4 v = shp[t + j * 32];
                s.x += v.x; s.y += v.y; s.z += v.z; s.w += v.w;
            }
            reinterpret_cast<float4*>(g_partial)[(size_t)sidx * 32 + t] = s;
        }
        __syncthreads();
    }

    grid_barrier(0);

    // ---------------- Phase 2: excite on blocks 0..255 ----------------------
    // Block (b = bid/8, rchunk = bid%8) handles r in [rchunk*256, +256).
    if (bid < NEXCITE) {
        const int b = bid >> 3;
        const int rchunk = bid & 7;

        // a) reduce pool partials -> mean s[128] (L2-resident, 50 KB/batch)
        if (t < C) {
            const float* p = g_partial + (size_t)b * NSPLIT * C + t;
            float acc = 0.f;
#pragma unroll 14
            for (int k = 0; k < NSPLIT; k++) acc += p[(size_t)k * C];
            s_mean[t] = acc * (1.0f / (float)HW);
        }
        __syncthreads();

        // b) GEMM1 + tanh-approx GELU: one r per thread (coalesced w1 columns)
        {
            const int r = rchunk * 256 + t;
            float acc = b1[r];
#pragma unroll 16
            for (int c = 0; c < C; c++) acc += s_mean[c] * w1[(size_t)c * R + r];
            float u = acc;
            float inner = 0.7978845608028654f * (u + 0.044715f * u * u * u);
            h_sh[t] = 0.5f * u * (1.0f + tanhf(inner));
        }
        __syncthreads();

        // c) GEMM2 partial over this 256-r chunk: c = t%128, half = t/128
        {
            const int c = t & (C - 1);
            const int half = t >> 7;
            const int rbase = rchunk * 256 + half * 128;
            const float* w2s = w2 + (size_t)rbase * C + c;
            float acc = 0.f;
#pragma unroll 16
            for (int rr = 0; rr < 128; rr++)
                acc += h_sh[half * 128 + rr] * w2s[(size_t)rr * C];
            red[t] = acc;
        }
        __syncthreads();
        if (t < C)
            g_gp[((size_t)b * 8 + rchunk) * C + t] = red[t] + red[t + 128];
    }

    grid_barrier(1);

    // ---------------- Phase 3: scale, statically reversed order -------------
    const int c4 = (t * 4) & (C - 1);    // fixed channel group per thread
    for (unsigned i = bid; i < NTOTAL; i += GRID) {
        const unsigned sidx = (NTOTAL - 1) - i;        // reverse of pool order
        const int b = sidx / NSPLIT;
        const int split = sidx % NSPLIT;

        // gate finalize for this thread's 4 channels (g_gp is L2-hot)
        float4 a = *reinterpret_cast<const float4*>(b2 + c4);
#pragma unroll
        for (int j = 0; j < 8; j++) {
            float4 p = *reinterpret_cast<const float4*>(g_gp + ((size_t)b * 8 + j) * C + c4);
            a.x += p.x; a.y += p.y; a.z += p.z; a.w += p.w;
        }
        float4 g4;
        g4.x = 1.0f / (1.0f + __expf(-a.x));
        g4.y = 1.0f / (1.0f + __expf(-a.y));
        g4.z = 1.0f / (1.0f + __expf(-a.z));
        g4.w = 1.0f / (1.0f + __expf(-a.w));

        const size_t base = (size_t)b * F4_PER_B + (size_t)split * F4_PER_BLK;
        const float4* __restrict__ xi = reinterpret_cast<const float4*>(x) + base;
        float4* __restrict__ xo = reinterpret_cast<float4*>(out) + base;
#pragma unroll
        for (int k = 0; k < 16; k++) {
            float4 v = __ldcs(&xi[t + k * TPB]);       // dead after use
            v.x *= g4.x; v.y *= g4.y; v.z *= g4.z; v.w *= g4.w;
            __stcs(&xo[t + k * TPB], v);               // streaming store
        }
    }
}

extern "C" void kernel_launch(void* const* d_in, const int* in_sizes, int n_in,
                              void* d_out, int out_size) {
    const float* x  = (const float*)d_in[0];
    const float* w1 = (const float*)d_in[1];
    const float* b1 = (const float*)d_in[2];
    const float* w2 = (const float*)d_in[3];
    const float* b2 = (const float*)d_in[4];
    float* out = (float*)d_out;

    se_persistent_kernel<<<GRID, TPB>>>(x, w1, b1, w2, b2, out);
}

// round 9
// speedup vs baseline: 1.7023x; 1.1189x over previous
#include <cuda_runtime.h>
#include <math.h>

// Shapes
// x:  [32, 112, 112, 128] fp32  -> B=32, HW=12544, C=128
// w1: [128, 2048], b1: [2048], w2: [2048, 128], b2: [128]
#define B      32
#define HW     12544
#define C      128
#define R      2048
#define NSPLIT 98
#define NTOTAL (B * NSPLIT)                  // 3136 splits
#define F4_PER_B  (HW * C / 4)               // 401408 float4 per batch
#define F4_PER_BLK (128 * C / 4)             // 4096 float4 per split
#define RBLKS  (R / 128)                     // 16 excite blocks per batch
#define CACHE_CUT (NTOTAL - 1500)            // last 1500 splits (~96 MB) L2-kept

// Scratch (device globals: allocation-free)
__device__ __align__(16) float g_partial[NTOTAL * C];   // 1.6 MB pool partials
__device__ __align__(16) float g_gp[B * RBLKS * C];     // gate partials, 256 KB

// ---------------------------------------------------------------------------
// Kernel 1: partial pooling sums.  grid (NSPLIT, B), 256 threads.
// Channel group per thread is fixed (256 % 32 == 0).  Splits the scale
// kernel will touch LAST are read evict-first (__ldcs) so the tail of x —
// which the reversed scale kernel reads FIRST — stays L2-resident.
// ---------------------------------------------------------------------------
__global__ __launch_bounds__(256, 8)
void se_pool_kernel(const float* __restrict__ x) {
    const int b = blockIdx.y;
    const int split = blockIdx.x;
    const unsigned sidx = (unsigned)b * NSPLIT + split;
    const float4* __restrict__ xb =
        reinterpret_cast<const float4*>(x) + (size_t)b * F4_PER_B + (size_t)split * F4_PER_BLK;
    const int t = threadIdx.x;

    float4 acc = make_float4(0.f, 0.f, 0.f, 0.f);
    if (sidx < CACHE_CUT) {
#pragma unroll
        for (int i = 0; i < 16; i++) {       // evict-first: don't pollute L2
            float4 v = __ldcs(&xb[t + i * 256]);
            acc.x += v.x; acc.y += v.y; acc.z += v.z; acc.w += v.w;
        }
    } else {
#pragma unroll
        for (int i = 0; i < 16; i++) {       // keep: scale reads these first
            float4 v = xb[t + i * 256];
            acc.x += v.x; acc.y += v.y; acc.z += v.z; acc.w += v.w;
        }
    }

    __shared__ float4 sh[256];
    sh[t] = acc;
    __syncthreads();

    if (t < 32) {
        float4 s = sh[t];
#pragma unroll
        for (int j = 1; j < 8; j++) {
            float4 v = sh[t + j * 32];
            s.x += v.x; s.y += v.y; s.z += v.z; s.w += v.w;
        }
        reinterpret_cast<float4*>(g_partial)[(size_t)sidx * 32 + t] = s;
    }
}

// ---------------------------------------------------------------------------
// Kernel 2: fused excite.  grid (RBLKS=16, B), 128 threads.
//   a) redundantly reduce this batch's pool partials (50 KB, L2-hit) -> s[128]
//   b) GEMM1 + tanh-GELU for r in [rblk*128, +128) -> h in shared
//   c) GEMM2 partial: gp[c] = sum_{r in chunk} h[r] * w2[r][c]
// ---------------------------------------------------------------------------
__global__ __launch_bounds__(128, 8)
void se_excite_kernel(const float* __restrict__ w1, const float* __restrict__ b1,
                      const float* __restrict__ w2) {
    const int b = blockIdx.y;
    const int rblk = blockIdx.x;
    const int t = threadIdx.x;

    __shared__ float s[C];
    __shared__ float h[128];

    {
        const float* p = g_partial + (size_t)b * NSPLIT * C + t;
        float acc = 0.f;
#pragma unroll 14
        for (int k = 0; k < NSPLIT; k++) acc += p[(size_t)k * C];
        s[t] = acc * (1.0f / (float)HW);
    }
    __syncthreads();

    {
        const int r = rblk * 128 + t;
        float acc = b1[r];
#pragma unroll 16
        for (int c = 0; c < C; c++) acc += s[c] * w1[(size_t)c * R + r];
        float u = acc;
        float inner = 0.7978845608028654f * (u + 0.044715f * u * u * u);
        h[t] = 0.5f * u * (1.0f + tanhf(inner));
    }
    __syncthreads();

    {
        const float* w2s = w2 + (size_t)(rblk * 128) * C + t;
        float acc = 0.f;
#pragma unroll 16
        for (int rr = 0; rr < 128; rr++) acc += h[rr] * w2s[(size_t)rr * C];
        g_gp[((size_t)b * RBLKS + rblk) * C + t] = acc;
    }
}

// ---------------------------------------------------------------------------
// Kernel 3: scale with fused gate finalize.  grid (NTOTAL), 256 threads.
// Traverses x in REVERSE of pool order so pool's L2-resident tail is hit.
// ---------------------------------------------------------------------------
__global__ __launch_bounds__(256, 8)
void se_scale_kernel(const float* __restrict__ x, const float* __restrict__ b2,
                     float* __restrict__ out) {
    const int rid = (NTOTAL - 1) - blockIdx.x;   // reversed traversal
    const int b   = rid / NSPLIT;
    const int blk = rid % NSPLIT;
    const int t = threadIdx.x;

    // gate for this thread's fixed 4-channel group
    const int c4 = (t * 4) & (C - 1);
    float4 g4;
    {
        float4 a = *reinterpret_cast<const float4*>(b2 + c4);
#pragma unroll
        for (int j = 0; j < RBLKS; j++) {
            float4 p = *reinterpret_cast<const float4*>(g_gp + ((size_t)b * RBLKS + j) * C + c4);
            a.x += p.x; a.y += p.y; a.z += p.z; a.w += p.w;
        }
        g4.x = 1.0f / (1.0f + __expf(-a.x));
        g4.y = 1.0f / (1.0f + __expf(-a.y));
        g4.z = 1.0f / (1.0f + __expf(-a.z));
        g4.w = 1.0f / (1.0f + __expf(-a.w));
    }

    const size_t base = (size_t)b * F4_PER_B + (size_t)blk * F4_PER_BLK;
    const float4* __restrict__ xi = reinterpret_cast<const float4*>(x) + base;
    float4* __restrict__ xo = reinterpret_cast<float4*>(out) + base;

#pragma unroll
    for (int i = 0; i < 16; i++) {
        float4 v = __ldcs(&xi[t + i * 256]);   // dead after use: evict-first
        v.x *= g4.x; v.y *= g4.y; v.z *= g4.z; v.w *= g4.w;
        __stcs(&xo[t + i * 256], v);           // streaming store
    }
}

extern "C" void kernel_launch(void* const* d_in, const int* in_sizes, int n_in,
                              void* d_out, int out_size) {
    const float* x  = (const float*)d_in[0];
    const float* w1 = (const float*)d_in[1];
    const float* b1 = (const float*)d_in[2];
    const float* w2 = (const float*)d_in[3];
    const float* b2 = (const float*)d_in[4];
    float* out = (float*)d_out;

    se_pool_kernel<<<dim3(NSPLIT, B), 256>>>(x);
    se_excite_kernel<<<dim3(RBLKS, B), 128>>>(w1, b1, w2);
    se_scale_kernel<<<NTOTAL, 256>>>(x, b2, out);
}

// round 10
// speedup vs baseline: 1.7283x; 1.0153x over previous
#include <cuda_runtime.h>
#include <math.h>

// Shapes
// x:  [32, 112, 112, 128] fp32  -> B=32, HW=12544, C=128
// w1: [128, 2048], b1: [2048], w2: [2048, 128], b2: [128]
#define B      32
#define HW     12544
#define C      128
#define R      2048
#define NSPLIT 98
#define NTOTAL (B * NSPLIT)                  // 3136 splits
#define F4_PER_B  (HW * C / 4)               // 401408 float4 per batch
#define F4_PER_BLK (128 * C / 4)             // 4096 float4 per split
#define RBLKS  (R / 128)                     // 16 excite blocks per batch

// Scratch (device globals: allocation-free)
__device__ __align__(16) float g_partial[NTOTAL * C];   // 1.6 MB pool partials
__device__ __align__(16) float g_gp[B * RBLKS * C];     // gate partials, 256 KB

// ---------------------------------------------------------------------------
// Kernel 1: partial pooling sums.  grid (NSPLIT, B), 256 threads.
// Channel group per thread is fixed (256 % 32 == 0): each thread accumulates
// one float4 of 4 channels across its rows.  (R5 version — no cache hints;
// R9 showed explicit L2 steering here doesn't help.)
// ---------------------------------------------------------------------------
__global__ __launch_bounds__(256, 8)
void se_pool_kernel(const float* __restrict__ x) {
    const int b = blockIdx.y;
    const int split = blockIdx.x;
    const float4* __restrict__ xb =
        reinterpret_cast<const float4*>(x) + (size_t)b * F4_PER_B + (size_t)split * F4_PER_BLK;
    const int t = threadIdx.x;

    float4 acc = make_float4(0.f, 0.f, 0.f, 0.f);
#pragma unroll
    for (int i = 0; i < 16; i++) {           // 16 * 256 = 4096 float4
        float4 v = xb[t + i * 256];
        acc.x += v.x; acc.y += v.y; acc.z += v.z; acc.w += v.w;
    }

    __shared__ float4 sh[256];
    sh[t] = acc;
    __syncthreads();

    if (t < 32) {
        float4 s = sh[t];
#pragma unroll
        for (int j = 1; j < 8; j++) {
            float4 v = sh[t + j * 32];
            s.x += v.x; s.y += v.y; s.z += v.z; s.w += v.w;
        }
        reinterpret_cast<float4*>(g_partial)[(size_t)(b * NSPLIT + split) * 32 + t] = s;
    }
}

// ---------------------------------------------------------------------------
// Kernel 2: fused excite.  grid (RBLKS=16, B), 128 threads.
//   a) redundantly reduce this batch's pool partials (50 KB, L2-hit) -> s[128]
//   b) GEMM1 + tanh-GELU for r in [rblk*128, +128) -> h in shared
//   c) GEMM2 partial: gp[c] = sum_{r in chunk} h[r] * w2[r][c]
// ---------------------------------------------------------------------------
__global__ __launch_bounds__(128, 8)
void se_excite_kernel(const float* __restrict__ w1, const float* __restrict__ b1,
                      const float* __restrict__ w2) {
    const int b = blockIdx.y;
    const int rblk = blockIdx.x;
    const int t = threadIdx.x;

    __shared__ float s[C];
    __shared__ float h[128];

    {
        const float* p = g_partial + (size_t)b * NSPLIT * C + t;
        float acc = 0.f;
#pragma unroll 14
        for (int k = 0; k < NSPLIT; k++) acc += p[(size_t)k * C];
        s[t] = acc * (1.0f / (float)HW);
    }
    __syncthreads();

    {
        const int r = rblk * 128 + t;
        float acc = b1[r];
#pragma unroll 16
        for (int c = 0; c < C; c++) acc += s[c] * w1[(size_t)c * R + r];
        float u = acc;
        float inner = 0.7978845608028654f * (u + 0.044715f * u * u * u);
        h[t] = 0.5f * u * (1.0f + tanhf(inner));
    }
    __syncthreads();

    {
        const float* w2s = w2 + (size_t)(rblk * 128) * C + t;
        float acc = 0.f;
#pragma unroll 16
        for (int rr = 0; rr < 128; rr++) acc += h[rr] * w2s[(size_t)rr * C];
        g_gp[((size_t)b * RBLKS + rblk) * C + t] = acc;
    }
}

// ---------------------------------------------------------------------------
// Kernel 3: scale with fused gate finalize.  grid (NTOTAL), 256 threads.
// Reversed traversal (hits pool's L2-resident tail).  Loads batched 4-deep
// before stores so the SASS front-loads independent LDG.128s; launch bounds
// relaxed to 6 blocks/SM so ptxas has ~42 regs for the batch.
// ---------------------------------------------------------------------------
__global__ __launch_bounds__(256, 6)
void se_scale_kernel(const float* __restrict__ x, const float* __restrict__ b2,
                     float* __restrict__ out) {
    const int rid = (NTOTAL - 1) - blockIdx.x;   // reversed traversal
    const int b   = rid / NSPLIT;
    const int blk = rid % NSPLIT;
    const int t = threadIdx.x;

    // gate for this thread's fixed 4-channel group (g_gp / b2 are L2-hot)
    const int c4 = (t * 4) & (C - 1);
    float4 g4;
    {
        float4 a = *reinterpret_cast<const float4*>(b2 + c4);
#pragma unroll
        for (int j = 0; j < RBLKS; j++) {
            float4 p = *reinterpret_cast<const float4*>(g_gp + ((size_t)b * RBLKS + j) * C + c4);
            a.x += p.x; a.y += p.y; a.z += p.z; a.w += p.w;
        }
        g4.x = 1.0f / (1.0f + __expf(-a.x));
        g4.y = 1.0f / (1.0f + __expf(-a.y));
        g4.z = 1.0f / (1.0f + __expf(-a.z));
        g4.w = 1.0f / (1.0f + __expf(-a.w));
    }

    const size_t base = (size_t)b * F4_PER_B + (size_t)blk * F4_PER_BLK;
    const float4* __restrict__ xi = reinterpret_cast<const float4*>(x) + base;
    float4* __restrict__ xo = reinterpret_cast<float4*>(out) + base;

#pragma unroll
    for (int g = 0; g < 4; g++) {
        float4 v0 = __ldcs(&xi[t + (g * 4 + 0) * 256]);
        float4 v1 = __ldcs(&xi[t + (g * 4 + 1) * 256]);
        float4 v2 = __ldcs(&xi[t + (g * 4 + 2) * 256]);
        float4 v3 = __ldcs(&xi[t + (g * 4 + 3) * 256]);
        v0.x *= g4.x; v0.y *= g4.y; v0.z *= g4.z; v0.w *= g4.w;
        v1.x *= g4.x; v1.y *= g4.y; v1.z *= g4.z; v1.w *= g4.w;
        v2.x *= g4.x; v2.y *= g4.y; v2.z *= g4.z; v2.w *= g4.w;
        v3.x *= g4.x; v3.y *= g4.y; v3.z *= g4.z; v3.w *= g4.w;
        __stcs(&xo[t + (g * 4 + 0) * 256], v0);
        __stcs(&xo[t + (g * 4 + 1) * 256], v1);
        __stcs(&xo[t + (g * 4 + 2) * 256], v2);
        __stcs(&xo[t + (g * 4 + 3) * 256], v3);
    }
}

extern "C" void kernel_launch(void* const* d_in, const int* in_sizes, int n_in,
                              void* d_out, int out_size) {
    const float* x  = (const float*)d_in[0];
    const float* w1 = (const float*)d_in[1];
    const float* b1 = (const float*)d_in[2];
    const float* w2 = (const float*)d_in[3];
    const float* b2 = (const float*)d_in[4];
    float* out = (float*)d_out;

    se_pool_kernel<<<dim3(NSPLIT, B), 256>>>(x);
    se_excite_kernel<<<dim3(RBLKS, B), 128>>>(w1, b1, w2);
    se_scale_kernel<<<NTOTAL, 256>>>(x, b2, out);
}